// round 13
// baseline (speedup 1.0000x reference)
#include <cuda_runtime.h>

#define CN 100000
#define CE 1600000
#define NB 391            // ceil(CN/256)
#define NSUB 64000        // S*M subgraph-node entries

typedef unsigned long long ull;

// ---- static scratch ----
__device__ ull   d_degcnt[CN];                 // hi32: cnt, lo32: fixed-point deg sum
__device__ float d_dinv[CN];
__device__ int   d_bsum[NB];
__device__ int   d_ptr[CN + 1];
__device__ int   d_pos[CN];
__device__ int   d_flag[CN];                   // node appears in subG_node?
__device__ int   d_nlist[CN];                  // compacted flagged nodes
__device__ int   d_ncnt;
__device__ ull   d_edge[CE];                   // packed (ew<<32 | src)
__device__ float d_hw[(size_t)2 * CN * 64];    // [c][n][64], dinv-scaled
__device__ float d_agg[(size_t)2 * CN * 64];
__device__ float d_g[(size_t)CN * 64];
__device__ float d_emb[(size_t)CN * 64];       // only flagged nodes written (rest stay 0)
__device__ float d_stats[256];                 // [c][sum64|sumsq64]

// ---- packed f32x2 helpers ----
__device__ __forceinline__ ull pk2(float a, float b) {
    ull r; asm("mov.b64 %0, {%1, %2};" : "=l"(r) : "f"(a), "f"(b)); return r;
}
__device__ __forceinline__ ull ffma2(ull a, ull b, ull c) {
    ull d; asm("fma.rn.f32x2 %0, %1, %2, %3;" : "=l"(d) : "l"(a), "l"(b), "l"(c)); return d;
}
__device__ __forceinline__ ull fmul2(ull a, ull b) {
    ull d; asm("mul.rn.f32x2 %0, %1, %2;" : "=l"(d) : "l"(a), "l"(b)); return d;
}

// ---- init ----
__global__ void init_k() {
    int n = blockIdx.x * 256 + threadIdx.x;
    if (n < CN) { d_degcnt[n] = 0ull; d_flag[n] = 0; }
    if (blockIdx.x == 0) d_stats[threadIdx.x] = 0.0f;
    if (blockIdx.x == 0 && threadIdx.x == 0) d_ncnt = 0;
}

// ---- edge pass 1: histogram + (first 64K threads) mark pooled nodes ----
__global__ void edge1_k(const int* __restrict__ dst, const float* __restrict__ ew,
                        const int* __restrict__ subG) {
    int e = blockIdx.x * 256 + threadIdx.x;
    if (e < NSUB) d_flag[subG[e]] = 1;
    if (e < CE) {
        unsigned fx = (unsigned)__float2uint_rn(ew[e] * 16777216.0f);
        atomicAdd(&d_degcnt[dst[e]], (1ull << 32) | (ull)fx);
    }
}

// ---- scan1: dinv + per-block count sums + compact flagged-node list ----
__global__ __launch_bounds__(256) void scan1_k() {
    __shared__ int sh[256];
    int i = blockIdx.x * 256 + threadIdx.x;
    int lane = threadIdx.x & 31;
    int cnt = 0;
    bool flagged = false;
    if (i < CN) {
        ull dc = d_degcnt[i];
        cnt = (int)(dc >> 32);
        float deg = 1.0f + (float)(unsigned)dc * 5.9604644775390625e-8f;
        d_dinv[i] = rsqrtf(deg);
        flagged = (d_flag[i] != 0);
    }
    // warp-aggregated append of flagged nodes
    unsigned m = __ballot_sync(0xffffffffu, flagged);
    if (m) {
        int leader = __ffs(m) - 1;
        int base = 0;
        if (lane == leader) base = atomicAdd(&d_ncnt, __popc(m));
        base = __shfl_sync(0xffffffffu, base, leader);
        if (flagged) d_nlist[base + __popc(m & ((1u << lane) - 1u))] = i;
    }
    sh[threadIdx.x] = cnt;
    __syncthreads();
    for (int off = 128; off; off >>= 1) {
        if (threadIdx.x < off) sh[threadIdx.x] += sh[threadIdx.x + off];
        __syncthreads();
    }
    if (threadIdx.x == 0) d_bsum[blockIdx.x] = sh[0];
}

// ---- scan3: per-block offset (redundant reduce) + local scan -> ptr/pos ----
__global__ __launch_bounds__(256) void scan3_k() {
    __shared__ int red[256];
    __shared__ int sh[256];
    __shared__ int boff_s;
    int t = threadIdx.x, b = blockIdx.x;
    int s = 0;
    if (t < b && t < NB) s = d_bsum[t];
    if (t + 256 < b) s += d_bsum[t + 256];
    red[t] = s;
    __syncthreads();
    for (int off = 128; off; off >>= 1) {
        if (t < off) red[t] += red[t + off];
        __syncthreads();
    }
    if (t == 0) boff_s = red[0];
    int i = b * 256 + t;
    int v = (i < CN) ? (int)(d_degcnt[i] >> 32) : 0;
    sh[t] = v;
    __syncthreads();
    for (int off = 1; off < 256; off <<= 1) {
        int u = (t >= off) ? sh[t - off] : 0;
        __syncthreads();
        sh[t] += u;
        __syncthreads();
    }
    if (i < CN) {
        int p = boff_s + sh[t] - v;
        d_ptr[i] = p;
        d_pos[i] = p;
        if (i == CN - 1) d_ptr[CN] = p + v;
    }
}

// ---- CSR fill: one packed 8B entry per edge ----
__global__ void fill_k(const int* __restrict__ src, const int* __restrict__ dst,
                       const float* __restrict__ ew) {
    int e = blockIdx.x * 256 + threadIdx.x;
    if (e >= CE) return;
    int d = dst[e];
    int p = atomicAdd(&d_pos[d], 1);
    d_edge[p] = ((ull)__float_as_uint(ew[e]) << 32) | (unsigned)src[e];
}

// ---- GEMM layer 1 (4-node register tile): hws_c = dinv * (x_c @ W1) ----
__global__ __launch_bounds__(256) void gemm0_k(const float* __restrict__ x,
                                               const float* __restrict__ W) {
    __shared__ ull Ws2[64 * 40];
    int tid = threadIdx.x, c = blockIdx.y;
    const ull* Wv = (const ull*)W;
    for (int i = tid; i < 2048; i += 256) {
        int k = i >> 5, j = i & 31;
        Ws2[k * 40 + (j >> 3) * 10 + (j & 7)] = Wv[i];
    }
    __syncthreads();
    int tx = tid & 3, tp = tid >> 2;
    int n0 = blockIdx.x * 256 + tp * 4;
    if (n0 >= CN) return;
    const float* rows[4];
    #pragma unroll
    for (int u = 0; u < 4; u++) {
        int n = min(n0 + u, CN - 1);
        rows[u] = x + (size_t)n * 128 + c * 64;
    }
    ull acc[4][8];
    #pragma unroll
    for (int u = 0; u < 4; u++)
        #pragma unroll
        for (int j = 0; j < 8; j++) acc[u][j] = 0ull;
    #pragma unroll
    for (int ch = 0; ch < 16; ch++) {
        float4 xa[4];
        #pragma unroll
        for (int u = 0; u < 4; u++) xa[u] = *(const float4*)(rows[u] + ch * 4);
        #pragma unroll
        for (int kk = 0; kk < 4; kk++) {
            int k = ch * 4 + kk;
            const ulonglong2* wq = (const ulonglong2*)(Ws2 + k * 40 + tx * 10);
            ulonglong2 w0 = wq[0], w1 = wq[1], w2 = wq[2], w3 = wq[3];
            #pragma unroll
            for (int u = 0; u < 4; u++) {
                float xv = ((const float*)&xa[u])[kk];
                ull x2 = pk2(xv, xv);
                acc[u][0] = ffma2(x2, w0.x, acc[u][0]);
                acc[u][1] = ffma2(x2, w0.y, acc[u][1]);
                acc[u][2] = ffma2(x2, w1.x, acc[u][2]);
                acc[u][3] = ffma2(x2, w1.y, acc[u][3]);
                acc[u][4] = ffma2(x2, w2.x, acc[u][4]);
                acc[u][5] = ffma2(x2, w2.y, acc[u][5]);
                acc[u][6] = ffma2(x2, w3.x, acc[u][6]);
                acc[u][7] = ffma2(x2, w3.y, acc[u][7]);
            }
        }
    }
    #pragma unroll
    for (int u = 0; u < 4; u++) {
        int n = n0 + u;
        if (n < CN) {
            float dv = d_dinv[n];
            ull dv2 = pk2(dv, dv);
            ulonglong2* o = (ulonglong2*)(d_hw + ((size_t)c * CN + n) * 64);
            #pragma unroll
            for (int j = 0; j < 4; j++) {
                ulonglong2 w;
                w.x = fmul2(acc[u][2 * j], dv2);
                w.y = fmul2(acc[u][2 * j + 1], dv2);
                o[tx * 4 + j] = w;
            }
        }
    }
}

// ---- agg layer 1 (both channels): agg = dinv*(sum ew*hws[src] + hws[n]) + b1, + stats ----
__global__ __launch_bounds__(256) void agg1_k(const float* __restrict__ b1) {
    __shared__ float sb[64];
    __shared__ float psum[8 * 128];
    __shared__ float psq[8 * 128];
    int tid = threadIdx.x;
    if (tid < 64) sb[tid] = b1[tid];
    __syncthreads();
    int w = tid >> 5, lane = tid & 31;
    int c = lane >> 4, qq = lane & 15;
    int n = blockIdx.x * 8 + w;                       // 12500*8 == CN
    const float* hwb = d_hw + (size_t)c * CN * 64;
    float4 acc = *(const float4*)(hwb + (size_t)n * 64 + qq * 4);   // self
    int beg = d_ptr[n], end = d_ptr[n + 1];
    for (int i = beg; i < end; i += 4) {
        #pragma unroll
        for (int k = 0; k < 4; k++) {
            int idx = i + k;
            if (idx < end) {
                ull pe = d_edge[idx];
                int s = (int)(unsigned)pe;
                float ww = __uint_as_float((unsigned)(pe >> 32));
                float4 v = *(const float4*)(hwb + (size_t)s * 64 + qq * 4);
                acc.x = fmaf(ww, v.x, acc.x);
                acc.y = fmaf(ww, v.y, acc.y);
                acc.z = fmaf(ww, v.z, acc.z);
                acc.w = fmaf(ww, v.w, acc.w);
            }
        }
    }
    float dv = d_dinv[n];
    float4 b4 = *(const float4*)(sb + qq * 4);
    float4 fin;
    fin.x = fmaf(dv, acc.x, b4.x);
    fin.y = fmaf(dv, acc.y, b4.y);
    fin.z = fmaf(dv, acc.z, b4.z);
    fin.w = fmaf(dv, acc.w, b4.w);
    *(float4*)(d_agg + ((size_t)c * CN + n) * 64 + qq * 4) = fin;
    float* ps = psum + w * 128 + c * 64 + qq * 4;
    float* pq = psq + w * 128 + c * 64 + qq * 4;
    ps[0] = fin.x; ps[1] = fin.y; ps[2] = fin.z; ps[3] = fin.w;
    pq[0] = fin.x * fin.x; pq[1] = fin.y * fin.y;
    pq[2] = fin.z * fin.z; pq[3] = fin.w * fin.w;
    __syncthreads();
    if (tid < 128) {
        float s = 0.f, q = 0.f;
        #pragma unroll
        for (int u = 0; u < 8; u++) { s += psum[u * 128 + tid]; q += psq[u * 128 + tid]; }
        int c2 = tid >> 6, f = tid & 63;
        atomicAdd(&d_stats[c2 * 128 + f], s);
        atomicAdd(&d_stats[c2 * 128 + 64 + f], q);
    }
}

// ---- GEMM layer 2 (4-node tile, fused GraphNorm+ReLU, dinv epilogue) ----
__global__ __launch_bounds__(256) void gemm1_k(const float* __restrict__ W,
                                               const float* __restrict__ gnw,
                                               const float* __restrict__ gnb,
                                               const float* __restrict__ gnms) {
    __shared__ ull Ws2[64 * 40];
    __shared__ float2 ss0[64], ss1[64];       // (0.5*scale, 0.5*shift) per channel
    int tid = threadIdx.x;
    const ull* Wv = (const ull*)W;
    for (int i = tid; i < 2048; i += 256) {
        int k = i >> 5, j = i & 31;
        Ws2[k * 40 + (j >> 3) * 10 + (j & 7)] = Wv[i];
    }
    if (tid < 128) {
        int c = tid >> 6, f = tid & 63;
        const float invN = 1.0f / CN;
        float mean = d_stats[c * 128 + f] * invN;
        float ex2 = d_stats[c * 128 + 64 + f] * invN;
        float ms = gnms[f];
        float var = ex2 - ms * (2.0f - ms) * mean * mean;
        float scale = gnw[f] * rsqrtf(var + 1e-5f);
        float shift = gnb[f] - scale * ms * mean;
        float2 v = make_float2(0.5f * scale, 0.5f * shift);
        if (c == 0) ss0[f] = v; else ss1[f] = v;
    }
    __syncthreads();
    int tx = tid & 3, tp = tid >> 2;
    int n0 = blockIdx.x * 256 + tp * 4;
    if (n0 >= CN) return;
    const float* r0[4];
    const float* r1[4];
    #pragma unroll
    for (int u = 0; u < 4; u++) {
        int n = min(n0 + u, CN - 1);
        r0[u] = d_agg + (size_t)n * 64;
        r1[u] = d_agg + ((size_t)CN + n) * 64;
    }
    ull acc[4][8];
    #pragma unroll
    for (int u = 0; u < 4; u++)
        #pragma unroll
        for (int j = 0; j < 8; j++) acc[u][j] = 0ull;
    #pragma unroll
    for (int ch = 0; ch < 16; ch++) {
        float4 a0[4], a1[4];
        #pragma unroll
        for (int u = 0; u < 4; u++) {
            a0[u] = *(const float4*)(r0[u] + ch * 4);
            a1[u] = *(const float4*)(r1[u] + ch * 4);
        }
        #pragma unroll
        for (int kk = 0; kk < 4; kk++) {
            int k = ch * 4 + kk;
            float2 s0 = ss0[k], s1 = ss1[k];
            const ulonglong2* wq = (const ulonglong2*)(Ws2 + k * 40 + tx * 10);
            ulonglong2 w0 = wq[0], w1 = wq[1], w2 = wq[2], w3 = wq[3];
            #pragma unroll
            for (int u = 0; u < 4; u++) {
                float v0 = ((const float*)&a0[u])[kk];
                float v1 = ((const float*)&a1[u])[kk];
                float xv = fmaxf(fmaf(s0.x, v0, s0.y), 0.f) +
                           fmaxf(fmaf(s1.x, v1, s1.y), 0.f);
                ull x2 = pk2(xv, xv);
                acc[u][0] = ffma2(x2, w0.x, acc[u][0]);
                acc[u][1] = ffma2(x2, w0.y, acc[u][1]);
                acc[u][2] = ffma2(x2, w1.x, acc[u][2]);
                acc[u][3] = ffma2(x2, w1.y, acc[u][3]);
                acc[u][4] = ffma2(x2, w2.x, acc[u][4]);
                acc[u][5] = ffma2(x2, w2.y, acc[u][5]);
                acc[u][6] = ffma2(x2, w3.x, acc[u][6]);
                acc[u][7] = ffma2(x2, w3.y, acc[u][7]);
            }
        }
    }
    #pragma unroll
    for (int u = 0; u < 4; u++) {
        int n = n0 + u;
        if (n < CN) {
            float dv = d_dinv[n];
            ull dv2 = pk2(dv, dv);
            ulonglong2* o = (ulonglong2*)(d_g + (size_t)n * 64);
            #pragma unroll
            for (int j = 0; j < 4; j++) {
                ulonglong2 w;
                w.x = fmul2(acc[u][2 * j], dv2);
                w.y = fmul2(acc[u][2 * j + 1], dv2);
                o[tx * 4 + j] = w;
            }
        }
    }
}

// ---- agg layer 2 (compacted pooled-node list): emb = dinv*(sum ew*g[src] + g[n]) + b2 ----
__global__ __launch_bounds__(256) void agg2_k(const float* __restrict__ b2) {
    __shared__ float sb[64];
    if (threadIdx.x < 64) sb[threadIdx.x] = b2[threadIdx.x];
    __syncthreads();
    int cnt = d_ncnt;
    int slot = threadIdx.x >> 4, qq = threadIdx.x & 15;
    int li = blockIdx.x * 16 + slot;                  // 6250 blocks cover worst case
    if (li >= cnt) return;
    int n = d_nlist[li];
    float4 acc = *(const float4*)(d_g + (size_t)n * 64 + qq * 4);   // self
    int beg = d_ptr[n], end = d_ptr[n + 1];
    for (int i = beg; i < end; i += 4) {
        #pragma unroll
        for (int k = 0; k < 4; k++) {
            int idx = i + k;
            if (idx < end) {
                ull pe = d_edge[idx];
                int s = (int)(unsigned)pe;
                float ww = __uint_as_float((unsigned)(pe >> 32));
                float4 v = *(const float4*)(d_g + (size_t)s * 64 + qq * 4);
                acc.x = fmaf(ww, v.x, acc.x);
                acc.y = fmaf(ww, v.y, acc.y);
                acc.z = fmaf(ww, v.z, acc.z);
                acc.w = fmaf(ww, v.w, acc.w);
            }
        }
    }
    float dv = d_dinv[n];
    float4 b4 = *(const float4*)(sb + qq * 4);
    float4 fin;
    fin.x = fmaf(dv, acc.x, b4.x);
    fin.y = fmaf(dv, acc.y, b4.y);
    fin.z = fmaf(dv, acc.z, b4.z);
    fin.w = fmaf(dv, acc.w, b4.w);
    *(float4*)(d_emb + (size_t)n * 64 + qq * 4) = fin;
}

// ---- subgraph pool + MLP: 4 subgraphs per block (amortize Wm stage) ----
__global__ __launch_bounds__(128) void pool_k(const int* __restrict__ subG,
                                              const float* __restrict__ mW1,
                                              const float* __restrict__ mb1,
                                              const float* __restrict__ mW2,
                                              const float* __restrict__ mb2,
                                              float* __restrict__ out) {
    __shared__ float Wm[64 * 128];
    __shared__ float pooled[64];
    __shared__ float ptmp[128];
    __shared__ float red[4];
    int tid = threadIdx.x;
    const float4* wv = (const float4*)mW1;
    #pragma unroll
    for (int i = 0; i < 16; i++) ((float4*)Wm)[tid + i * 128] = wv[tid + i * 128];
    float bias1 = mb1[tid];
    float w2 = mW2[tid];
    int j = tid & 63, half = tid >> 6;
    for (int sg = 0; sg < 4; sg++) {
        int s = blockIdx.x * 4 + sg;
        float p = 0.f;
        #pragma unroll 4
        for (int m = half * 32; m < half * 32 + 32; m++) {
            int node = subG[s * 64 + m];
            p += d_emb[(size_t)node * 64 + j];
        }
        __syncthreads();
        ptmp[tid] = p;
        __syncthreads();
        if (tid < 64) pooled[tid] = ptmp[tid] + ptmp[tid + 64];
        __syncthreads();
        float acc = bias1;
        #pragma unroll 8
        for (int o = 0; o < 64; o++) acc = fmaf(pooled[o], Wm[o * 128 + tid], acc);
        float contrib = fmaxf(acc, 0.f) * w2;
        #pragma unroll
        for (int off = 16; off; off >>= 1) contrib += __shfl_xor_sync(0xffffffffu, contrib, off);
        if ((tid & 31) == 0) red[tid >> 5] = contrib;
        __syncthreads();
        if (tid == 0) out[s] = red[0] + red[1] + red[2] + red[3] + mb2[0];
    }
}

extern "C" void kernel_launch(void* const* d_in, const int* in_sizes, int n_in,
                              void* d_out, int out_size) {
    const float* x    = (const float*)d_in[0];
    const int*   ei   = (const int*)d_in[1];
    const float* ew   = (const float*)d_in[2];
    const int*   subG = (const int*)d_in[3];
    const float* W1   = (const float*)d_in[4];
    const float* b1   = (const float*)d_in[5];
    const float* gnw  = (const float*)d_in[6];
    const float* gnb  = (const float*)d_in[7];
    const float* gnms = (const float*)d_in[8];
    const float* W2   = (const float*)d_in[9];
    const float* b2   = (const float*)d_in[10];
    const float* mW1  = (const float*)d_in[11];
    const float* mb1  = (const float*)d_in[12];
    const float* mW2  = (const float*)d_in[13];
    const float* mb2  = (const float*)d_in[14];
    float* out = (float*)d_out;
    const int* src = ei;
    const int* dst = ei + CE;

    const int eb = (CE + 255) / 256;

    init_k<<<NB, 256>>>();
    edge1_k<<<eb, 256>>>(dst, ew, subG);
    scan1_k<<<NB, 256>>>();
    scan3_k<<<NB, 256>>>();
    fill_k<<<eb, 256>>>(src, dst, ew);

    dim3 g0(NB, 2);
    gemm0_k<<<g0, 256>>>(x, W1);
    agg1_k<<<CN / 8, 256>>>(b1);
    gemm1_k<<<NB, 256>>>(W2, gnw, gnb, gnms);
    agg2_k<<<CN / 16, 256>>>(b2);
    pool_k<<<250, 128>>>(subG, mW1, mb1, mW2, mb2, out);
}

// round 14
// speedup vs baseline: 1.1735x; 1.1735x over previous
#include <cuda_runtime.h>

#define CN 100000
#define CE 1600000
#define NB 391            // ceil(CN/256)
#define NSUB 64000        // S*M subgraph-node entries

typedef unsigned long long ull;

// ---- static scratch ----
__device__ ull   d_degcnt[CN];                 // hi32: cnt, lo32: fixed-point deg sum
__device__ float d_dinv[CN];
__device__ int   d_bsum[NB];
__device__ int   d_ptr[CN + 1];
__device__ int   d_pos[CN];
__device__ int   d_flag[CN];                   // node appears in subG_node?
__device__ ull   d_edge[CE];                   // packed (ew<<32 | src)
__device__ float d_hw[(size_t)CN * 128];       // interleaved [n][c*64+f], dinv-scaled
__device__ float d_agg[(size_t)CN * 128];      // interleaved [n][c*64+f]
__device__ float d_g[(size_t)CN * 64];
__device__ float d_emb[(size_t)CN * 64];       // only flagged nodes written (rest stay 0)
__device__ float d_stats[256];                 // [c][sum64|sumsq64]

// ---- packed f32x2 helpers ----
__device__ __forceinline__ ull pk2(float a, float b) {
    ull r; asm("mov.b64 %0, {%1, %2};" : "=l"(r) : "f"(a), "f"(b)); return r;
}
__device__ __forceinline__ ull ffma2(ull a, ull b, ull c) {
    ull d; asm("fma.rn.f32x2 %0, %1, %2, %3;" : "=l"(d) : "l"(a), "l"(b), "l"(c)); return d;
}
__device__ __forceinline__ ull fmul2(ull a, ull b) {
    ull d; asm("mul.rn.f32x2 %0, %1, %2;" : "=l"(d) : "l"(a), "l"(b)); return d;
}

// ---- init ----
__global__ void init_k() {
    int n = blockIdx.x * 256 + threadIdx.x;
    if (n < CN) { d_degcnt[n] = 0ull; d_flag[n] = 0; }
    if (blockIdx.x == 0) d_stats[threadIdx.x] = 0.0f;
}

// ---- edge pass 1: histogram + (first 64K threads) mark pooled nodes ----
__global__ void edge1_k(const int* __restrict__ dst, const float* __restrict__ ew,
                        const int* __restrict__ subG) {
    int e = blockIdx.x * 256 + threadIdx.x;
    if (e < NSUB) d_flag[subG[e]] = 1;
    if (e < CE) {
        unsigned fx = (unsigned)__float2uint_rn(ew[e] * 16777216.0f);
        atomicAdd(&d_degcnt[dst[e]], (1ull << 32) | (ull)fx);
    }
}

// ---- scan1: dinv + per-block count sums ----
__global__ __launch_bounds__(256) void scan1_k() {
    __shared__ int sh[256];
    int i = blockIdx.x * 256 + threadIdx.x;
    int cnt = 0;
    if (i < CN) {
        ull dc = d_degcnt[i];
        cnt = (int)(dc >> 32);
        float deg = 1.0f + (float)(unsigned)dc * 5.9604644775390625e-8f;
        d_dinv[i] = rsqrtf(deg);
    }
    sh[threadIdx.x] = cnt;
    __syncthreads();
    for (int off = 128; off; off >>= 1) {
        if (threadIdx.x < off) sh[threadIdx.x] += sh[threadIdx.x + off];
        __syncthreads();
    }
    if (threadIdx.x == 0) d_bsum[blockIdx.x] = sh[0];
}

// ---- scan3: per-block offset (redundant reduce) + local scan -> ptr/pos ----
__global__ __launch_bounds__(256) void scan3_k() {
    __shared__ int red[256];
    __shared__ int sh[256];
    __shared__ int boff_s;
    int t = threadIdx.x, b = blockIdx.x;
    int s = 0;
    if (t < b && t < NB) s = d_bsum[t];
    if (t + 256 < b) s += d_bsum[t + 256];
    red[t] = s;
    __syncthreads();
    for (int off = 128; off; off >>= 1) {
        if (t < off) red[t] += red[t + off];
        __syncthreads();
    }
    if (t == 0) boff_s = red[0];
    int i = b * 256 + t;
    int v = (i < CN) ? (int)(d_degcnt[i] >> 32) : 0;
    sh[t] = v;
    __syncthreads();
    for (int off = 1; off < 256; off <<= 1) {
        int u = (t >= off) ? sh[t - off] : 0;
        __syncthreads();
        sh[t] += u;
        __syncthreads();
    }
    if (i < CN) {
        int p = boff_s + sh[t] - v;
        d_ptr[i] = p;
        d_pos[i] = p;
        if (i == CN - 1) d_ptr[CN] = p + v;
    }
}

// ---- CSR fill: one packed 8B entry per edge ----
__global__ void fill_k(const int* __restrict__ src, const int* __restrict__ dst,
                       const float* __restrict__ ew) {
    int e = blockIdx.x * 256 + threadIdx.x;
    if (e >= CE) return;
    int d = dst[e];
    int p = atomicAdd(&d_pos[d], 1);
    d_edge[p] = ((ull)__float_as_uint(ew[e]) << 32) | (unsigned)src[e];
}

// ---- GEMM layer 1 (4-node register tile): hw[n][c*64+..] = dinv * (x_c @ W1) ----
__global__ __launch_bounds__(256) void gemm0_k(const float* __restrict__ x,
                                               const float* __restrict__ W) {
    __shared__ ull Ws2[64 * 40];
    int tid = threadIdx.x, c = blockIdx.y;
    const ull* Wv = (const ull*)W;
    for (int i = tid; i < 2048; i += 256) {
        int k = i >> 5, j = i & 31;
        Ws2[k * 40 + (j >> 3) * 10 + (j & 7)] = Wv[i];
    }
    __syncthreads();
    int tx = tid & 3, tp = tid >> 2;
    int n0 = blockIdx.x * 256 + tp * 4;
    if (n0 >= CN) return;
    const float* rows[4];
    #pragma unroll
    for (int u = 0; u < 4; u++) {
        int n = min(n0 + u, CN - 1);
        rows[u] = x + (size_t)n * 128 + c * 64;
    }
    ull acc[4][8];
    #pragma unroll
    for (int u = 0; u < 4; u++)
        #pragma unroll
        for (int j = 0; j < 8; j++) acc[u][j] = 0ull;
    #pragma unroll
    for (int ch = 0; ch < 16; ch++) {
        float4 xa[4];
        #pragma unroll
        for (int u = 0; u < 4; u++) xa[u] = *(const float4*)(rows[u] + ch * 4);
        #pragma unroll
        for (int kk = 0; kk < 4; kk++) {
            int k = ch * 4 + kk;
            const ulonglong2* wq = (const ulonglong2*)(Ws2 + k * 40 + tx * 10);
            ulonglong2 w0 = wq[0], w1 = wq[1], w2 = wq[2], w3 = wq[3];
            #pragma unroll
            for (int u = 0; u < 4; u++) {
                float xv = ((const float*)&xa[u])[kk];
                ull x2 = pk2(xv, xv);
                acc[u][0] = ffma2(x2, w0.x, acc[u][0]);
                acc[u][1] = ffma2(x2, w0.y, acc[u][1]);
                acc[u][2] = ffma2(x2, w1.x, acc[u][2]);
                acc[u][3] = ffma2(x2, w1.y, acc[u][3]);
                acc[u][4] = ffma2(x2, w2.x, acc[u][4]);
                acc[u][5] = ffma2(x2, w2.y, acc[u][5]);
                acc[u][6] = ffma2(x2, w3.x, acc[u][6]);
                acc[u][7] = ffma2(x2, w3.y, acc[u][7]);
            }
        }
    }
    #pragma unroll
    for (int u = 0; u < 4; u++) {
        int n = n0 + u;
        if (n < CN) {
            float dv = d_dinv[n];
            ull dv2 = pk2(dv, dv);
            ulonglong2* o = (ulonglong2*)(d_hw + (size_t)n * 128 + c * 64);
            #pragma unroll
            for (int j = 0; j < 4; j++) {
                ulonglong2 w;
                w.x = fmul2(acc[u][2 * j], dv2);
                w.y = fmul2(acc[u][2 * j + 1], dv2);
                o[tx * 4 + j] = w;
            }
        }
    }
}

// ---- agg layer 1: warp/node, ONE 512B row per edge; agg = dv*(...)+b1, + stats ----
__global__ __launch_bounds__(256) void agg1_k(const float* __restrict__ b1) {
    __shared__ float sb[64];
    __shared__ float psum[8 * 128];
    __shared__ float psq[8 * 128];
    int tid = threadIdx.x;
    if (tid < 64) sb[tid] = b1[tid];
    __syncthreads();
    int w = tid >> 5, lane = tid & 31;
    int qq = lane & 15;
    int n = blockIdx.x * 8 + w;                       // 12500*8 == CN
    float4 acc = *(const float4*)(d_hw + (size_t)n * 128 + lane * 4);   // self
    int beg = d_ptr[n], end = d_ptr[n + 1];
    int e4 = beg + ((end - beg) & ~3);
    int i = beg;
    for (; i < e4; i += 4) {
        #pragma unroll
        for (int k = 0; k < 4; k++) {
            ull pe = d_edge[i + k];
            int s = (int)(unsigned)pe;
            float ww = __uint_as_float((unsigned)(pe >> 32));
            float4 v = *(const float4*)(d_hw + (size_t)s * 128 + lane * 4);
            acc.x = fmaf(ww, v.x, acc.x);
            acc.y = fmaf(ww, v.y, acc.y);
            acc.z = fmaf(ww, v.z, acc.z);
            acc.w = fmaf(ww, v.w, acc.w);
        }
    }
    for (; i < end; i++) {
        ull pe = d_edge[i];
        int s = (int)(unsigned)pe;
        float ww = __uint_as_float((unsigned)(pe >> 32));
        float4 v = *(const float4*)(d_hw + (size_t)s * 128 + lane * 4);
        acc.x = fmaf(ww, v.x, acc.x);
        acc.y = fmaf(ww, v.y, acc.y);
        acc.z = fmaf(ww, v.z, acc.z);
        acc.w = fmaf(ww, v.w, acc.w);
    }
    float dv = d_dinv[n];
    float4 b4 = *(const float4*)(sb + qq * 4);
    float4 fin;
    fin.x = fmaf(dv, acc.x, b4.x);
    fin.y = fmaf(dv, acc.y, b4.y);
    fin.z = fmaf(dv, acc.z, b4.z);
    fin.w = fmaf(dv, acc.w, b4.w);
    *(float4*)(d_agg + (size_t)n * 128 + lane * 4) = fin;
    float* ps = psum + w * 128 + lane * 4;              // lane*4 == c*64+qq*4
    float* pq = psq + w * 128 + lane * 4;
    ps[0] = fin.x; ps[1] = fin.y; ps[2] = fin.z; ps[3] = fin.w;
    pq[0] = fin.x * fin.x; pq[1] = fin.y * fin.y;
    pq[2] = fin.z * fin.z; pq[3] = fin.w * fin.w;
    __syncthreads();
    if (tid < 128) {
        float s = 0.f, q = 0.f;
        #pragma unroll
        for (int u = 0; u < 8; u++) { s += psum[u * 128 + tid]; q += psq[u * 128 + tid]; }
        int c2 = tid >> 6, f = tid & 63;
        atomicAdd(&d_stats[c2 * 128 + f], s);
        atomicAdd(&d_stats[c2 * 128 + 64 + f], q);
    }
}

// ---- GEMM layer 2 (4-node tile, fused GraphNorm+ReLU, dinv epilogue) ----
__global__ __launch_bounds__(256) void gemm1_k(const float* __restrict__ W,
                                               const float* __restrict__ gnw,
                                               const float* __restrict__ gnb,
                                               const float* __restrict__ gnms) {
    __shared__ ull Ws2[64 * 40];
    __shared__ float2 ss0[64], ss1[64];       // (0.5*scale, 0.5*shift) per channel
    int tid = threadIdx.x;
    const ull* Wv = (const ull*)W;
    for (int i = tid; i < 2048; i += 256) {
        int k = i >> 5, j = i & 31;
        Ws2[k * 40 + (j >> 3) * 10 + (j & 7)] = Wv[i];
    }
    if (tid < 128) {
        int c = tid >> 6, f = tid & 63;
        const float invN = 1.0f / CN;
        float mean = d_stats[c * 128 + f] * invN;
        float ex2 = d_stats[c * 128 + 64 + f] * invN;
        float ms = gnms[f];
        float var = ex2 - ms * (2.0f - ms) * mean * mean;
        float scale = gnw[f] * rsqrtf(var + 1e-5f);
        float shift = gnb[f] - scale * ms * mean;
        float2 v = make_float2(0.5f * scale, 0.5f * shift);
        if (c == 0) ss0[f] = v; else ss1[f] = v;
    }
    __syncthreads();
    int tx = tid & 3, tp = tid >> 2;
    int n0 = blockIdx.x * 256 + tp * 4;
    if (n0 >= CN) return;
    const float* r0[4];
    #pragma unroll
    for (int u = 0; u < 4; u++) {
        int n = min(n0 + u, CN - 1);
        r0[u] = d_agg + (size_t)n * 128;               // ch1 at +64, same 512B row
    }
    ull acc[4][8];
    #pragma unroll
    for (int u = 0; u < 4; u++)
        #pragma unroll
        for (int j = 0; j < 8; j++) acc[u][j] = 0ull;
    #pragma unroll
    for (int ch = 0; ch < 16; ch++) {
        float4 a0[4], a1[4];
        #pragma unroll
        for (int u = 0; u < 4; u++) {
            a0[u] = *(const float4*)(r0[u] + ch * 4);
            a1[u] = *(const float4*)(r0[u] + 64 + ch * 4);
        }
        #pragma unroll
        for (int kk = 0; kk < 4; kk++) {
            int k = ch * 4 + kk;
            float2 s0 = ss0[k], s1 = ss1[k];
            const ulonglong2* wq = (const ulonglong2*)(Ws2 + k * 40 + tx * 10);
            ulonglong2 w0 = wq[0], w1 = wq[1], w2 = wq[2], w3 = wq[3];
            #pragma unroll
            for (int u = 0; u < 4; u++) {
                float v0 = ((const float*)&a0[u])[kk];
                float v1 = ((const float*)&a1[u])[kk];
                float xv = fmaxf(fmaf(s0.x, v0, s0.y), 0.f) +
                           fmaxf(fmaf(s1.x, v1, s1.y), 0.f);
                ull x2 = pk2(xv, xv);
                acc[u][0] = ffma2(x2, w0.x, acc[u][0]);
                acc[u][1] = ffma2(x2, w0.y, acc[u][1]);
                acc[u][2] = ffma2(x2, w1.x, acc[u][2]);
                acc[u][3] = ffma2(x2, w1.y, acc[u][3]);
                acc[u][4] = ffma2(x2, w2.x, acc[u][4]);
                acc[u][5] = ffma2(x2, w2.y, acc[u][5]);
                acc[u][6] = ffma2(x2, w3.x, acc[u][6]);
                acc[u][7] = ffma2(x2, w3.y, acc[u][7]);
            }
        }
    }
    #pragma unroll
    for (int u = 0; u < 4; u++) {
        int n = n0 + u;
        if (n < CN) {
            float dv = d_dinv[n];
            ull dv2 = pk2(dv, dv);
            ulonglong2* o = (ulonglong2*)(d_g + (size_t)n * 64);
            #pragma unroll
            for (int j = 0; j < 4; j++) {
                ulonglong2 w;
                w.x = fmul2(acc[u][2 * j], dv2);
                w.y = fmul2(acc[u][2 * j + 1], dv2);
                o[tx * 4 + j] = w;
            }
        }
    }
}

// ---- agg layer 2 (flag skip, in-order): emb = dinv*(sum ew*g[src] + g[n]) + b2 ----
__global__ __launch_bounds__(256) void agg2_k(const float* __restrict__ b2) {
    __shared__ float sb[64];
    if (threadIdx.x < 64) sb[threadIdx.x] = b2[threadIdx.x];
    __syncthreads();
    int slot = threadIdx.x >> 4, qq = threadIdx.x & 15;
    int n = blockIdx.x * 16 + slot;                   // 6250*16 == CN
    if (d_flag[n] == 0) return;                       // node never pooled -> skip
    float4 acc = *(const float4*)(d_g + (size_t)n * 64 + qq * 4);   // self
    int beg = d_ptr[n], end = d_ptr[n + 1];
    int e4 = beg + ((end - beg) & ~3);
    int i = beg;
    for (; i < e4; i += 4) {
        #pragma unroll
        for (int k = 0; k < 4; k++) {
            ull pe = d_edge[i + k];
            int s = (int)(unsigned)pe;
            float ww = __uint_as_float((unsigned)(pe >> 32));
            float4 v = *(const float4*)(d_g + (size_t)s * 64 + qq * 4);
            acc.x = fmaf(ww, v.x, acc.x);
            acc.y = fmaf(ww, v.y, acc.y);
            acc.z = fmaf(ww, v.z, acc.z);
            acc.w = fmaf(ww, v.w, acc.w);
        }
    }
    for (; i < end; i++) {
        ull pe = d_edge[i];
        int s = (int)(unsigned)pe;
        float ww = __uint_as_float((unsigned)(pe >> 32));
        float4 v = *(const float4*)(d_g + (size_t)s * 64 + qq * 4);
        acc.x = fmaf(ww, v.x, acc.x);
        acc.y = fmaf(ww, v.y, acc.y);
        acc.z = fmaf(ww, v.z, acc.z);
        acc.w = fmaf(ww, v.w, acc.w);
    }
    float dv = d_dinv[n];
    float4 b4 = *(const float4*)(sb + qq * 4);
    float4 fin;
    fin.x = fmaf(dv, acc.x, b4.x);
    fin.y = fmaf(dv, acc.y, b4.y);
    fin.z = fmaf(dv, acc.z, b4.z);
    fin.w = fmaf(dv, acc.w, b4.w);
    *(float4*)(d_emb + (size_t)n * 64 + qq * 4) = fin;
}

// ---- subgraph pool + MLP ----
__global__ __launch_bounds__(128) void pool_k(const int* __restrict__ subG,
                                              const float* __restrict__ mW1,
                                              const float* __restrict__ mb1,
                                              const float* __restrict__ mW2,
                                              const float* __restrict__ mb2,
                                              float* __restrict__ out) {
    __shared__ float Wm[64 * 128];
    __shared__ float pooled[64];
    __shared__ float ptmp[128];
    __shared__ float red[4];
    int tid = threadIdx.x, s = blockIdx.x;
    const float4* wv = (const float4*)mW1;
    #pragma unroll
    for (int i = 0; i < 16; i++) ((float4*)Wm)[tid + i * 128] = wv[tid + i * 128];
    int j = tid & 63, half = tid >> 6;
    float p = 0.f;
    #pragma unroll 4
    for (int m = half * 32; m < half * 32 + 32; m++) {
        int node = subG[s * 64 + m];
        p += d_emb[(size_t)node * 64 + j];
    }
    ptmp[tid] = p;
    __syncthreads();
    if (tid < 64) pooled[tid] = ptmp[tid] + ptmp[tid + 64];
    __syncthreads();
    float acc = mb1[tid];
    #pragma unroll 8
    for (int o = 0; o < 64; o++) acc = fmaf(pooled[o], Wm[o * 128 + tid], acc);
    float contrib = fmaxf(acc, 0.f) * mW2[tid];
    #pragma unroll
    for (int off = 16; off; off >>= 1) contrib += __shfl_xor_sync(0xffffffffu, contrib, off);
    if ((tid & 31) == 0) red[tid >> 5] = contrib;
    __syncthreads();
    if (tid == 0) out[s] = red[0] + red[1] + red[2] + red[3] + mb2[0];
}

extern "C" void kernel_launch(void* const* d_in, const int* in_sizes, int n_in,
                              void* d_out, int out_size) {
    const float* x    = (const float*)d_in[0];
    const int*   ei   = (const int*)d_in[1];
    const float* ew   = (const float*)d_in[2];
    const int*   subG = (const int*)d_in[3];
    const float* W1   = (const float*)d_in[4];
    const float* b1   = (const float*)d_in[5];
    const float* gnw  = (const float*)d_in[6];
    const float* gnb  = (const float*)d_in[7];
    const float* gnms = (const float*)d_in[8];
    const float* W2   = (const float*)d_in[9];
    const float* b2   = (const float*)d_in[10];
    const float* mW1  = (const float*)d_in[11];
    const float* mb1  = (const float*)d_in[12];
    const float* mW2  = (const float*)d_in[13];
    const float* mb2  = (const float*)d_in[14];
    float* out = (float*)d_out;
    const int* src = ei;
    const int* dst = ei + CE;

    const int eb = (CE + 255) / 256;

    init_k<<<NB, 256>>>();
    edge1_k<<<eb, 256>>>(dst, ew, subG);
    scan1_k<<<NB, 256>>>();
    scan3_k<<<NB, 256>>>();
    fill_k<<<eb, 256>>>(src, dst, ew);

    dim3 g0(NB, 2);
    gemm0_k<<<g0, 256>>>(x, W1);
    agg1_k<<<CN / 8, 256>>>(b1);
    gemm1_k<<<NB, 256>>>(W2, gnw, gnb, gnms);
    agg2_k<<<CN / 16, 256>>>(b2);
    pool_k<<<1000, 128>>>(subG, mW1, mb1, mW2, mb2, out);
}

// round 15
// speedup vs baseline: 1.3104x; 1.1167x over previous
#include <cuda_runtime.h>

#define CN 100000
#define CE 1600000
#define NB 391            // ceil(CN/256)
#define NSUB 64000        // S*M subgraph-node entries

typedef unsigned long long ull;

// ---- static scratch ----
__device__ int   d_cnt[CN];                    // in-degree histogram
__device__ float d_dinv[CN];
__device__ int   d_bsum[NB];
__device__ int   d_ptr[CN + 1];
__device__ int   d_pos[CN];
__device__ int   d_flag[CN];                   // node appears in subG_node?
__device__ ull   d_edge[CE];                   // packed (ew<<32 | src)
__device__ float d_hw[(size_t)2 * CN * 64];    // [c][n][64], dinv-scaled
__device__ float d_agg[(size_t)2 * CN * 64];
__device__ float d_g[(size_t)CN * 64];
__device__ float d_emb[(size_t)CN * 64];       // only flagged nodes written (rest stay 0)
__device__ float d_stats[256];                 // [c][sum64|sumsq64]

// ---- packed f32x2 helpers ----
__device__ __forceinline__ ull pk2(float a, float b) {
    ull r; asm("mov.b64 %0, {%1, %2};" : "=l"(r) : "f"(a), "f"(b)); return r;
}
__device__ __forceinline__ ull ffma2(ull a, ull b, ull c) {
    ull d; asm("fma.rn.f32x2 %0, %1, %2, %3;" : "=l"(d) : "l"(a), "l"(b), "l"(c)); return d;
}
__device__ __forceinline__ ull fmul2(ull a, ull b) {
    ull d; asm("mul.rn.f32x2 %0, %1, %2;" : "=l"(d) : "l"(a), "l"(b)); return d;
}

// ---- init ----
__global__ void init_k() {
    int n = blockIdx.x * 256 + threadIdx.x;
    if (n < CN) { d_cnt[n] = 0; d_flag[n] = 0; }
    if (blockIdx.x == 0) d_stats[threadIdx.x] = 0.0f;
}

// ---- edge pass 1: 32-bit count histogram + (first 64K threads) mark pooled nodes ----
__global__ void edge1_k(const int* __restrict__ dst, const int* __restrict__ subG) {
    int e = blockIdx.x * 256 + threadIdx.x;
    if (e < NSUB) d_flag[subG[e]] = 1;
    if (e < CE) atomicAdd(&d_cnt[dst[e]], 1);
}

// ---- scan1: per-block count sums ----
__global__ __launch_bounds__(256) void scan1_k() {
    __shared__ int sh[256];
    int i = blockIdx.x * 256 + threadIdx.x;
    sh[threadIdx.x] = (i < CN) ? d_cnt[i] : 0;
    __syncthreads();
    for (int off = 128; off; off >>= 1) {
        if (threadIdx.x < off) sh[threadIdx.x] += sh[threadIdx.x + off];
        __syncthreads();
    }
    if (threadIdx.x == 0) d_bsum[blockIdx.x] = sh[0];
}

// ---- scan3: per-block offset (redundant reduce) + local scan -> ptr/pos ----
__global__ __launch_bounds__(256) void scan3_k() {
    __shared__ int red[256];
    __shared__ int sh[256];
    __shared__ int boff_s;
    int t = threadIdx.x, b = blockIdx.x;
    int s = 0;
    if (t < b && t < NB) s = d_bsum[t];
    if (t + 256 < b) s += d_bsum[t + 256];
    red[t] = s;
    __syncthreads();
    for (int off = 128; off; off >>= 1) {
        if (t < off) red[t] += red[t + off];
        __syncthreads();
    }
    if (t == 0) boff_s = red[0];
    int i = b * 256 + t;
    int v = (i < CN) ? d_cnt[i] : 0;
    sh[t] = v;
    __syncthreads();
    for (int off = 1; off < 256; off <<= 1) {
        int u = (t >= off) ? sh[t - off] : 0;
        __syncthreads();
        sh[t] += u;
        __syncthreads();
    }
    if (i < CN) {
        int p = boff_s + sh[t] - v;
        d_ptr[i] = p;
        d_pos[i] = p;
        if (i == CN - 1) d_ptr[CN] = p + v;
    }
}

// ---- CSR fill: one packed 8B entry per edge ----
__global__ void fill_k(const int* __restrict__ src, const int* __restrict__ dst,
                       const float* __restrict__ ew) {
    int e = blockIdx.x * 256 + threadIdx.x;
    if (e >= CE) return;
    int d = dst[e];
    int p = atomicAdd(&d_pos[d], 1);
    d_edge[p] = ((ull)__float_as_uint(ew[e]) << 32) | (unsigned)src[e];
}

// ---- dinv: warp per node, coalesced CSR-bucket weight sum ----
__global__ __launch_bounds__(256) void dinv_k() {
    int w = threadIdx.x >> 5, lane = threadIdx.x & 31;
    int n = blockIdx.x * 8 + w;                       // 12500*8 == CN
    int beg = d_ptr[n], end = d_ptr[n + 1];
    float s = 0.f;
    for (int i = beg + lane; i < end; i += 32)
        s += __uint_as_float((unsigned)(d_edge[i] >> 32));
    #pragma unroll
    for (int off = 16; off; off >>= 1) s += __shfl_xor_sync(0xffffffffu, s, off);
    if (lane == 0) d_dinv[n] = rsqrtf(1.0f + s);
}

// ---- GEMM layer 1 (4-node register tile): hws_c = dinv * (x_c @ W1) ----
__global__ __launch_bounds__(256) void gemm0_k(const float* __restrict__ x,
                                               const float* __restrict__ W) {
    __shared__ ull Ws2[64 * 40];
    int tid = threadIdx.x, c = blockIdx.y;
    const ull* Wv = (const ull*)W;
    for (int i = tid; i < 2048; i += 256) {
        int k = i >> 5, j = i & 31;
        Ws2[k * 40 + (j >> 3) * 10 + (j & 7)] = Wv[i];
    }
    __syncthreads();
    int tx = tid & 3, tp = tid >> 2;
    int n0 = blockIdx.x * 256 + tp * 4;
    if (n0 >= CN) return;
    const float* rows[4];
    #pragma unroll
    for (int u = 0; u < 4; u++) {
        int n = min(n0 + u, CN - 1);
        rows[u] = x + (size_t)n * 128 + c * 64;
    }
    ull acc[4][8];
    #pragma unroll
    for (int u = 0; u < 4; u++)
        #pragma unroll
        for (int j = 0; j < 8; j++) acc[u][j] = 0ull;
    #pragma unroll
    for (int ch = 0; ch < 16; ch++) {
        float4 xa[4];
        #pragma unroll
        for (int u = 0; u < 4; u++) xa[u] = *(const float4*)(rows[u] + ch * 4);
        #pragma unroll
        for (int kk = 0; kk < 4; kk++) {
            int k = ch * 4 + kk;
            const ulonglong2* wq = (const ulonglong2*)(Ws2 + k * 40 + tx * 10);
            ulonglong2 w0 = wq[0], w1 = wq[1], w2 = wq[2], w3 = wq[3];
            #pragma unroll
            for (int u = 0; u < 4; u++) {
                float xv = ((const float*)&xa[u])[kk];
                ull x2 = pk2(xv, xv);
                acc[u][0] = ffma2(x2, w0.x, acc[u][0]);
                acc[u][1] = ffma2(x2, w0.y, acc[u][1]);
                acc[u][2] = ffma2(x2, w1.x, acc[u][2]);
                acc[u][3] = ffma2(x2, w1.y, acc[u][3]);
                acc[u][4] = ffma2(x2, w2.x, acc[u][4]);
                acc[u][5] = ffma2(x2, w2.y, acc[u][5]);
                acc[u][6] = ffma2(x2, w3.x, acc[u][6]);
                acc[u][7] = ffma2(x2, w3.y, acc[u][7]);
            }
        }
    }
    #pragma unroll
    for (int u = 0; u < 4; u++) {
        int n = n0 + u;
        if (n < CN) {
            float dv = d_dinv[n];
            ull dv2 = pk2(dv, dv);
            ulonglong2* o = (ulonglong2*)(d_hw + ((size_t)c * CN + n) * 64);
            #pragma unroll
            for (int j = 0; j < 4; j++) {
                ulonglong2 w;
                w.x = fmul2(acc[u][2 * j], dv2);
                w.y = fmul2(acc[u][2 * j + 1], dv2);
                o[tx * 4 + j] = w;
            }
        }
    }
}

// ---- agg layer 1 (both channels): agg = dinv*(sum ew*hws[src] + hws[n]) + b1, + stats ----
__global__ __launch_bounds__(256) void agg1_k(const float* __restrict__ b1) {
    __shared__ float sb[64];
    __shared__ float psum[8 * 128];
    __shared__ float psq[8 * 128];
    int tid = threadIdx.x;
    if (tid < 64) sb[tid] = b1[tid];
    __syncthreads();
    int w = tid >> 5, lane = tid & 31;
    int c = lane >> 4, qq = lane & 15;
    int n = blockIdx.x * 8 + w;                       // 12500*8 == CN
    const float* hwb = d_hw + (size_t)c * CN * 64;
    float4 acc = *(const float4*)(hwb + (size_t)n * 64 + qq * 4);   // self
    int beg = d_ptr[n], end = d_ptr[n + 1];
    int e4 = beg + ((end - beg) & ~3);
    int i = beg;
    for (; i < e4; i += 4) {
        #pragma unroll
        for (int k = 0; k < 4; k++) {
            ull pe = d_edge[i + k];
            int s = (int)(unsigned)pe;
            float ww = __uint_as_float((unsigned)(pe >> 32));
            float4 v = *(const float4*)(hwb + (size_t)s * 64 + qq * 4);
            acc.x = fmaf(ww, v.x, acc.x);
            acc.y = fmaf(ww, v.y, acc.y);
            acc.z = fmaf(ww, v.z, acc.z);
            acc.w = fmaf(ww, v.w, acc.w);
        }
    }
    for (; i < end; i++) {
        ull pe = d_edge[i];
        int s = (int)(unsigned)pe;
        float ww = __uint_as_float((unsigned)(pe >> 32));
        float4 v = *(const float4*)(hwb + (size_t)s * 64 + qq * 4);
        acc.x = fmaf(ww, v.x, acc.x);
        acc.y = fmaf(ww, v.y, acc.y);
        acc.z = fmaf(ww, v.z, acc.z);
        acc.w = fmaf(ww, v.w, acc.w);
    }
    float dv = d_dinv[n];
    float4 b4 = *(const float4*)(sb + qq * 4);
    float4 fin;
    fin.x = fmaf(dv, acc.x, b4.x);
    fin.y = fmaf(dv, acc.y, b4.y);
    fin.z = fmaf(dv, acc.z, b4.z);
    fin.w = fmaf(dv, acc.w, b4.w);
    *(float4*)(d_agg + ((size_t)c * CN + n) * 64 + qq * 4) = fin;
    float* ps = psum + w * 128 + c * 64 + qq * 4;
    float* pq = psq + w * 128 + c * 64 + qq * 4;
    ps[0] = fin.x; ps[1] = fin.y; ps[2] = fin.z; ps[3] = fin.w;
    pq[0] = fin.x * fin.x; pq[1] = fin.y * fin.y;
    pq[2] = fin.z * fin.z; pq[3] = fin.w * fin.w;
    __syncthreads();
    if (tid < 128) {
        float s = 0.f, q = 0.f;
        #pragma unroll
        for (int u = 0; u < 8; u++) { s += psum[u * 128 + tid]; q += psq[u * 128 + tid]; }
        int c2 = tid >> 6, f = tid & 63;
        atomicAdd(&d_stats[c2 * 128 + f], s);
        atomicAdd(&d_stats[c2 * 128 + 64 + f], q);
    }
}

// ---- GEMM layer 2 (4-node tile, fused GraphNorm+ReLU, dinv epilogue) ----
__global__ __launch_bounds__(256) void gemm1_k(const float* __restrict__ W,
                                               const float* __restrict__ gnw,
                                               const float* __restrict__ gnb,
                                               const float* __restrict__ gnms) {
    __shared__ ull Ws2[64 * 40];
    __shared__ float2 ss0[64], ss1[64];       // (0.5*scale, 0.5*shift) per channel
    int tid = threadIdx.x;
    const ull* Wv = (const ull*)W;
    for (int i = tid; i < 2048; i += 256) {
        int k = i >> 5, j = i & 31;
        Ws2[k * 40 + (j >> 3) * 10 + (j & 7)] = Wv[i];
    }
    if (tid < 128) {
        int c = tid >> 6, f = tid & 63;
        const float invN = 1.0f / CN;
        float mean = d_stats[c * 128 + f] * invN;
        float ex2 = d_stats[c * 128 + 64 + f] * invN;
        float ms = gnms[f];
        float var = ex2 - ms * (2.0f - ms) * mean * mean;
        float scale = gnw[f] * rsqrtf(var + 1e-5f);
        float shift = gnb[f] - scale * ms * mean;
        float2 v = make_float2(0.5f * scale, 0.5f * shift);
        if (c == 0) ss0[f] = v; else ss1[f] = v;
    }
    __syncthreads();
    int tx = tid & 3, tp = tid >> 2;
    int n0 = blockIdx.x * 256 + tp * 4;
    if (n0 >= CN) return;
    const float* r0[4];
    const float* r1[4];
    #pragma unroll
    for (int u = 0; u < 4; u++) {
        int n = min(n0 + u, CN - 1);
        r0[u] = d_agg + (size_t)n * 64;
        r1[u] = d_agg + ((size_t)CN + n) * 64;
    }
    ull acc[4][8];
    #pragma unroll
    for (int u = 0; u < 4; u++)
        #pragma unroll
        for (int j = 0; j < 8; j++) acc[u][j] = 0ull;
    #pragma unroll
    for (int ch = 0; ch < 16; ch++) {
        float4 a0[4], a1[4];
        #pragma unroll
        for (int u = 0; u < 4; u++) {
            a0[u] = *(const float4*)(r0[u] + ch * 4);
            a1[u] = *(const float4*)(r1[u] + ch * 4);
        }
        #pragma unroll
        for (int kk = 0; kk < 4; kk++) {
            int k = ch * 4 + kk;
            float2 s0 = ss0[k], s1 = ss1[k];
            const ulonglong2* wq = (const ulonglong2*)(Ws2 + k * 40 + tx * 10);
            ulonglong2 w0 = wq[0], w1 = wq[1], w2 = wq[2], w3 = wq[3];
            #pragma unroll
            for (int u = 0; u < 4; u++) {
                float v0 = ((const float*)&a0[u])[kk];
                float v1 = ((const float*)&a1[u])[kk];
                float xv = fmaxf(fmaf(s0.x, v0, s0.y), 0.f) +
                           fmaxf(fmaf(s1.x, v1, s1.y), 0.f);
                ull x2 = pk2(xv, xv);
                acc[u][0] = ffma2(x2, w0.x, acc[u][0]);
                acc[u][1] = ffma2(x2, w0.y, acc[u][1]);
                acc[u][2] = ffma2(x2, w1.x, acc[u][2]);
                acc[u][3] = ffma2(x2, w1.y, acc[u][3]);
                acc[u][4] = ffma2(x2, w2.x, acc[u][4]);
                acc[u][5] = ffma2(x2, w2.y, acc[u][5]);
                acc[u][6] = ffma2(x2, w3.x, acc[u][6]);
                acc[u][7] = ffma2(x2, w3.y, acc[u][7]);
            }
        }
    }
    #pragma unroll
    for (int u = 0; u < 4; u++) {
        int n = n0 + u;
        if (n < CN) {
            float dv = d_dinv[n];
            ull dv2 = pk2(dv, dv);
            ulonglong2* o = (ulonglong2*)(d_g + (size_t)n * 64);
            #pragma unroll
            for (int j = 0; j < 4; j++) {
                ulonglong2 w;
                w.x = fmul2(acc[u][2 * j], dv2);
                w.y = fmul2(acc[u][2 * j + 1], dv2);
                o[tx * 4 + j] = w;
            }
        }
    }
}

// ---- agg layer 2 (flag skip, in-order): emb = dinv*(sum ew*g[src] + g[n]) + b2 ----
__global__ __launch_bounds__(256) void agg2_k(const float* __restrict__ b2) {
    __shared__ float sb[64];
    if (threadIdx.x < 64) sb[threadIdx.x] = b2[threadIdx.x];
    __syncthreads();
    int slot = threadIdx.x >> 4, qq = threadIdx.x & 15;
    int n = blockIdx.x * 16 + slot;                   // 6250*16 == CN
    if (d_flag[n] == 0) return;                       // node never pooled -> skip
    float4 acc = *(const float4*)(d_g + (size_t)n * 64 + qq * 4);   // self
    int beg = d_ptr[n], end = d_ptr[n + 1];
    int e4 = beg + ((end - beg) & ~3);
    int i = beg;
    for (; i < e4; i += 4) {
        #pragma unroll
        for (int k = 0; k < 4; k++) {
            ull pe = d_edge[i + k];
            int s = (int)(unsigned)pe;
            float ww = __uint_as_float((unsigned)(pe >> 32));
            float4 v = *(const float4*)(d_g + (size_t)s * 64 + qq * 4);
            acc.x = fmaf(ww, v.x, acc.x);
            acc.y = fmaf(ww, v.y, acc.y);
            acc.z = fmaf(ww, v.z, acc.z);
            acc.w = fmaf(ww, v.w, acc.w);
        }
    }
    for (; i < end; i++) {
        ull pe = d_edge[i];
        int s = (int)(unsigned)pe;
        float ww = __uint_as_float((unsigned)(pe >> 32));
        float4 v = *(const float4*)(d_g + (size_t)s * 64 + qq * 4);
        acc.x = fmaf(ww, v.x, acc.x);
        acc.y = fmaf(ww, v.y, acc.y);
        acc.z = fmaf(ww, v.z, acc.z);
        acc.w = fmaf(ww, v.w, acc.w);
    }
    float dv = d_dinv[n];
    float4 b4 = *(const float4*)(sb + qq * 4);
    float4 fin;
    fin.x = fmaf(dv, acc.x, b4.x);
    fin.y = fmaf(dv, acc.y, b4.y);
    fin.z = fmaf(dv, acc.z, b4.z);
    fin.w = fmaf(dv, acc.w, b4.w);
    *(float4*)(d_emb + (size_t)n * 64 + qq * 4) = fin;
}

// ---- subgraph pool + MLP ----
__global__ __launch_bounds__(128) void pool_k(const int* __restrict__ subG,
                                              const float* __restrict__ mW1,
                                              const float* __restrict__ mb1,
                                              const float* __restrict__ mW2,
                                              const float* __restrict__ mb2,
                                              float* __restrict__ out) {
    __shared__ float Wm[64 * 128];
    __shared__ float pooled[64];
    __shared__ float ptmp[128];
    __shared__ float red[4];
    int tid = threadIdx.x, s = blockIdx.x;
    const float4* wv = (const float4*)mW1;
    #pragma unroll
    for (int i = 0; i < 16; i++) ((float4*)Wm)[tid + i * 128] = wv[tid + i * 128];
    int j = tid & 63, half = tid >> 6;
    float p = 0.f;
    #pragma unroll 4
    for (int m = half * 32; m < half * 32 + 32; m++) {
        int node = subG[s * 64 + m];
        p += d_emb[(size_t)node * 64 + j];
    }
    ptmp[tid] = p;
    __syncthreads();
    if (tid < 64) pooled[tid] = ptmp[tid] + ptmp[tid + 64];
    __syncthreads();
    float acc = mb1[tid];
    #pragma unroll 8
    for (int o = 0; o < 64; o++) acc = fmaf(pooled[o], Wm[o * 128 + tid], acc);
    float contrib = fmaxf(acc, 0.f) * mW2[tid];
    #pragma unroll
    for (int off = 16; off; off >>= 1) contrib += __shfl_xor_sync(0xffffffffu, contrib, off);
    if ((tid & 31) == 0) red[tid >> 5] = contrib;
    __syncthreads();
    if (tid == 0) out[s] = red[0] + red[1] + red[2] + red[3] + mb2[0];
}

extern "C" void kernel_launch(void* const* d_in, const int* in_sizes, int n_in,
                              void* d_out, int out_size) {
    const float* x    = (const float*)d_in[0];
    const int*   ei   = (const int*)d_in[1];
    const float* ew   = (const float*)d_in[2];
    const int*   subG = (const int*)d_in[3];
    const float* W1   = (const float*)d_in[4];
    const float* b1   = (const float*)d_in[5];
    const float* gnw  = (const float*)d_in[6];
    const float* gnb  = (const float*)d_in[7];
    const float* gnms = (const float*)d_in[8];
    const float* W2   = (const float*)d_in[9];
    const float* b2   = (const float*)d_in[10];
    const float* mW1  = (const float*)d_in[11];
    const float* mb1  = (const float*)d_in[12];
    const float* mW2  = (const float*)d_in[13];
    const float* mb2  = (const float*)d_in[14];
    float* out = (float*)d_out;
    const int* src = ei;
    const int* dst = ei + CE;

    const int eb = (CE + 255) / 256;

    init_k<<<NB, 256>>>();
    edge1_k<<<eb, 256>>>(dst, subG);
    scan1_k<<<NB, 256>>>();
    scan3_k<<<NB, 256>>>();
    fill_k<<<eb, 256>>>(src, dst, ew);
    dinv_k<<<CN / 8, 256>>>();

    dim3 g0(NB, 2);
    gemm0_k<<<g0, 256>>>(x, W1);
    agg1_k<<<CN / 8, 256>>>(b1);
    gemm1_k<<<NB, 256>>>(W2, gnw, gnb, gnms);
    agg2_k<<<CN / 16, 256>>>(b2);
    pool_k<<<1000, 128>>>(subG, mW1, mb1, mW2, mb2, out);
}